// round 8
// baseline (speedup 1.0000x reference)
#include <cuda_runtime.h>
#include <math_constants.h>

// Problem shape (fixed by the dataset)
#define BB 4
#define HH 32
#define DD 128
#define SS 8192
#define HG 4              // head-groups per batch (8 heads each)
#define HPG 8             // heads per group
#define NSPL 64           // splits -> grid = 4*4*64 = 1024 CTAs
#define NW 4              // warps per CTA; warp w owns heads hg*8 + 2w, +1
#define NBH (BB * HH)     // 128
#define SCALE 0.08838834764831845f   // 1/sqrt(128)

// Scratch for split-KV partials, indexed by (bh * NSPL + split)
__device__ float g_pm[NBH * NSPL];
__device__ float g_pl[NBH * NSPL];
__device__ float g_pacc[(size_t)NBH * NSPL * DD];
__device__ int   g_cnt[BB * HG];   // zero-init; self-resetting (graph-safe)

__device__ __forceinline__ float warp_sum(float v) {
#pragma unroll
    for (int o = 16; o > 0; o >>= 1)
        v += __shfl_xor_sync(0xffffffffu, v, o);
    return v;
}

__device__ __forceinline__ float dot4(const float4 a, const float4 b) {
    return a.x * b.x + a.y * b.y + a.z * b.z + a.w * b.w;
}

__device__ __forceinline__ float4 ldcs4(const float* p) {
    return __ldcs(reinterpret_cast<const float4*>(p));
}

// ---------------------------------------------------------------------------
// CTA = (b, head-group, split). Warp w owns 2 adjacent heads -> per position
// it reads 1KB CONTIGUOUS K (and 1KB V). 2-position unroll -> 16 float4
// streaming loads in flight (MLP_p1=8 per K/V stream, the measured sweet
// spot). The 4 warps cover 4KB of each 16KB row; the 4 head-group CTAs
// cover the full row.
// ---------------------------------------------------------------------------
__global__ __launch_bounds__(NW * 32)
void attn_split_kernel(const float* __restrict__ x,
                       const float* __restrict__ kv,
                       const int*   __restrict__ cur_pos,
                       float*       __restrict__ out) {
    const int bid   = blockIdx.x;                 // ((b*HG + hg)*NSPL + split)
    const int split = bid % NSPL;
    const int bg    = bid / NSPL;                 // b*HG + hg
    const int hg    = bg % HG;
    const int b     = bg / HG;

    const int tid  = threadIdx.x;
    const int lane = tid & 31;
    const int w    = tid >> 5;
    const int hA   = hg * HPG + w * 2;            // this warp's first head
    const int bhA  = b * HH + hA;

    const int len   = *cur_pos + 1;
    const int chunk = (len + NSPL - 1) / NSPL;
    const int s0    = split * chunk;
    const int s1    = min(len, s0 + chunk);

    // q for the warp's two heads (lane's 4 dims each)
    const float* qb = x + (size_t)bhA * DD + lane * 4;
    const float4 q0 = *reinterpret_cast<const float4*>(qb);
    const float4 q1 = *reinterpret_cast<const float4*>(qb + DD);

    const size_t rowHD   = (size_t)HH * DD;             // floats per position
    const size_t kv_half = (size_t)BB * SS * rowHD;     // K -> V offset
    // base of this warp's 1KB block within a position row
    const float* Kp = kv + (size_t)b * SS * rowHD + (size_t)hA * DD + lane * 4;
    const float* Vp = Kp + kv_half;

    float  m0 = -CUDART_INF_F, m1 = -CUDART_INF_F;
    float  l0 = 0.f, l1 = 0.f;
    float4 a0 = make_float4(0, 0, 0, 0), a1 = a0;

    int s = s0;
    // 2-position unroll: 8 K + 8 V float4 loads issued before dependent math.
    for (; s + 1 < s1; s += 2) {
        const float* kS = Kp + (size_t)s * rowHD;
        const float* kT = kS + rowHD;
        const float* vS = Vp + (size_t)s * rowHD;
        const float* vT = vS + rowHD;

        const float4 kS0 = ldcs4(kS);       const float4 kS1 = ldcs4(kS + DD);
        const float4 kT0 = ldcs4(kT);       const float4 kT1 = ldcs4(kT + DD);
        const float4 vS0 = ldcs4(vS);       const float4 vS1 = ldcs4(vS + DD);
        const float4 vT0 = ldcs4(vT);       const float4 vT1 = ldcs4(vT + DD);

        const float sS0 = warp_sum(dot4(kS0, q0)) * SCALE;
        const float sT0 = warp_sum(dot4(kT0, q0)) * SCALE;
        const float sS1 = warp_sum(dot4(kS1, q1)) * SCALE;
        const float sT1 = warp_sum(dot4(kT1, q1)) * SCALE;

        // head A
        {
            const float mn = fmaxf(m0, fmaxf(sS0, sT0));
            const float c  = __expf(m0 - mn);
            const float pS = __expf(sS0 - mn);
            const float pT = __expf(sT0 - mn);
            m0 = mn; l0 = l0 * c + (pS + pT);
            a0.x = a0.x * c + pS * vS0.x + pT * vT0.x;
            a0.y = a0.y * c + pS * vS0.y + pT * vT0.y;
            a0.z = a0.z * c + pS * vS0.z + pT * vT0.z;
            a0.w = a0.w * c + pS * vS0.w + pT * vT0.w;
        }
        // head B
        {
            const float mn = fmaxf(m1, fmaxf(sS1, sT1));
            const float c  = __expf(m1 - mn);
            const float pS = __expf(sS1 - mn);
            const float pT = __expf(sT1 - mn);
            m1 = mn; l1 = l1 * c + (pS + pT);
            a1.x = a1.x * c + pS * vS1.x + pT * vT1.x;
            a1.y = a1.y * c + pS * vS1.y + pT * vT1.y;
            a1.z = a1.z * c + pS * vS1.z + pT * vT1.z;
            a1.w = a1.w * c + pS * vS1.w + pT * vT1.w;
        }
    }
    // tail position (at most one)
    for (; s < s1; s++) {
        const float* kS = Kp + (size_t)s * rowHD;
        const float* vS = Vp + (size_t)s * rowHD;
        const float4 k0 = ldcs4(kS);  const float4 k1 = ldcs4(kS + DD);
        const float4 v0 = ldcs4(vS);  const float4 v1 = ldcs4(vS + DD);
        const float sc0 = warp_sum(dot4(k0, q0)) * SCALE;
        const float sc1 = warp_sum(dot4(k1, q1)) * SCALE;
        {
            const float mn = fmaxf(m0, sc0);
            const float c  = __expf(m0 - mn);
            const float p  = __expf(sc0 - mn);
            m0 = mn; l0 = l0 * c + p;
            a0.x = a0.x * c + p * v0.x; a0.y = a0.y * c + p * v0.y;
            a0.z = a0.z * c + p * v0.z; a0.w = a0.w * c + p * v0.w;
        }
        {
            const float mn = fmaxf(m1, sc1);
            const float c  = __expf(m1 - mn);
            const float p  = __expf(sc1 - mn);
            m1 = mn; l1 = l1 * c + p;
            a1.x = a1.x * c + p * v1.x; a1.y = a1.y * c + p * v1.y;
            a1.z = a1.z * c + p * v1.z; a1.w = a1.w * c + p * v1.w;
        }
    }

    // ---- write per-head partials (warps own disjoint heads: no CTA reduce) --
    {
        const int idxA = bhA * NSPL + split;          // head A
        const int idxB = idxA + NSPL;                 // head B = bhA+1
        if (lane == 0) {
            g_pm[idxA] = m0; g_pl[idxA] = l0;
            g_pm[idxB] = m1; g_pl[idxB] = l1;
        }
        reinterpret_cast<float4*>(g_pacc + (size_t)idxA * DD)[lane] = a0;
        reinterpret_cast<float4*>(g_pacc + (size_t)idxB * DD)[lane] = a1;
    }

    // ---- fused combine: last CTA per (b, head-group) merges all splits ----
    // ORDER MATTERS (R7 bug): ALL warps' partial stores must complete before
    // this CTA increments the counter — otherwise the combiner reads stale
    // partials from warps 1-3 of not-yet-finished CTAs.
    __syncthreads();       // all warps' stores done (CTA-wide)
    __threadfence();       // cumulative: make them globally visible before atomic
    __shared__ int s_last;
    if (tid == 0) s_last = (atomicAdd(&g_cnt[bg], 1) == NSPL - 1) ? 1 : 0;
    __syncthreads();

    if (s_last) {
#pragma unroll
        for (int j = 0; j < 2; j++) {
            const int bh = bhA + j;
            float M = -CUDART_INF_F;
#pragma unroll 8
            for (int i = 0; i < NSPL; i++)
                M = fmaxf(M, __ldcg(&g_pm[bh * NSPL + i]));

            float  L = 0.f;
            float4 o = make_float4(0, 0, 0, 0);
#pragma unroll 4
            for (int i = 0; i < NSPL; i++) {
                const int idx = bh * NSPL + i;
                const float li = __ldcg(&g_pl[idx]);
                if (li == 0.f) continue;
                const float c = __expf(__ldcg(&g_pm[idx]) - M);
                L += c * li;
                const float4 a = __ldcg(reinterpret_cast<const float4*>(
                    g_pacc + (size_t)idx * DD) + lane);
                o.x += c * a.x; o.y += c * a.y; o.z += c * a.z; o.w += c * a.w;
            }
            const float inv = 1.f / L;
            const float4 r = make_float4(o.x * inv, o.y * inv,
                                         o.z * inv, o.w * inv);
            reinterpret_cast<float4*>(out + (size_t)bh * DD)[lane] = r;
        }
        if (tid == 0) g_cnt[bg] = 0;   // reset for next graph replay
    }
}

// ---------------------------------------------------------------------------
extern "C" void kernel_launch(void* const* d_in, const int* in_sizes, int n_in,
                              void* d_out, int out_size) {
    // Identify inputs defensively by element count:
    //   x: B*H*D = 16384 fp32, kv: 2*B*S*H*D fp32 (largest), current_pos: 1 int
    const float* x  = nullptr;
    const float* kv = nullptr;
    const int*   cp = nullptr;
    long long best_kv = -1;
    for (int i = 0; i < n_in; i++) {
        if (in_sizes[i] == 1) cp = (const int*)d_in[i];
        else if (in_sizes[i] == BB * HH * DD) x = (const float*)d_in[i];
        else if ((long long)in_sizes[i] > best_kv) {
            best_kv = in_sizes[i];
            kv = (const float*)d_in[i];
        }
    }

    attn_split_kernel<<<BB * HG * NSPL, NW * 32>>>(x, kv, cp, (float*)d_out);
}

// round 9
// speedup vs baseline: 1.3110x; 1.3110x over previous
#include <cuda_runtime.h>
#include <math_constants.h>

// Problem shape (fixed by the dataset)
#define BB 4
#define HH 32
#define DD 128
#define SS 8192
#define NSPLITS 32        // grid = 128*32 = 4096 single-warp CTAs
#define NBH (BB * HH)     // 128
#define SCALE 0.08838834764831845f   // 1/sqrt(128)

// Scratch for split-KV partials (device globals: allocation-free)
__device__ float g_pm[NBH * NSPLITS];
__device__ float g_pl[NBH * NSPLITS];
__device__ float g_pacc[(size_t)NBH * NSPLITS * DD];
__device__ int   g_cnt[NBH];   // zero-init; self-resetting -> graph-replay safe

__device__ __forceinline__ float warp_sum(float v) {
#pragma unroll
    for (int o = 16; o > 0; o >>= 1)
        v += __shfl_xor_sync(0xffffffffu, v, o);
    return v;
}

__device__ __forceinline__ float dot4(const float4 a, const float4 b) {
    return a.x * b.x + a.y * b.y + a.z * b.z + a.w * b.w;
}

__device__ __forceinline__ float4 ldcs4(const float* p) {
    return __ldcs(reinterpret_cast<const float4*>(p));
}

// ---------------------------------------------------------------------------
// One single-warp CTA = one (b, h, split). Lane owns dims [4*lane, 4*lane+4).
// 4x position unroll -> 8 streaming float4 loads in flight (measured optimum).
// No intra-CTA reduce, no __syncthreads. The last CTA per (b,h) (atomic
// counter) merges all split partials and writes the final output.
// ---------------------------------------------------------------------------
__global__ __launch_bounds__(32)
void attn_split_kernel(const float* __restrict__ x,
                       const float* __restrict__ kv,
                       const int*   __restrict__ cur_pos,
                       float*       __restrict__ out) {
    const int bid   = blockIdx.x;            // bh*NSPLITS + split
    const int bh    = bid / NSPLITS;
    const int h     = bh % HH;
    const int b     = bh / HH;
    const int split = bid % NSPLITS;

    const int lane = threadIdx.x;

    const int len   = *cur_pos + 1;                      // valid positions
    const int chunk = (len + NSPLITS - 1) / NSPLITS;
    const int s0    = split * chunk;
    const int s1    = min(len, s0 + chunk);

    // q[b,0,h,:] — lane's 4 dims
    const float4 q = *reinterpret_cast<const float4*>(
        x + (size_t)(b * HH + h) * DD + lane * 4);

    const size_t row_stride = (size_t)HH * DD;           // stride over s
    const size_t kv_half    = (size_t)BB * SS * HH * DD; // K->V offset
    const float* Kp = kv + (size_t)b * SS * row_stride + (size_t)h * DD + lane * 4;
    const float* Vp = Kp + kv_half;

    float  m = -CUDART_INF_F;
    float  l = 0.f;
    float4 acc = make_float4(0.f, 0.f, 0.f, 0.f);

    int s = s0;
    // 4x unroll: 8 streaming float4 loads in flight before dependent math,
    // single max/rescale per group -> 4 independent __expf's.
    for (; s + 3 < s1; s += 4) {
        const float4 k0 = ldcs4(Kp + (size_t)(s    ) * row_stride);
        const float4 v0 = ldcs4(Vp + (size_t)(s    ) * row_stride);
        const float4 k1 = ldcs4(Kp + (size_t)(s + 1) * row_stride);
        const float4 v1 = ldcs4(Vp + (size_t)(s + 1) * row_stride);
        const float4 k2 = ldcs4(Kp + (size_t)(s + 2) * row_stride);
        const float4 v2 = ldcs4(Vp + (size_t)(s + 2) * row_stride);
        const float4 k3 = ldcs4(Kp + (size_t)(s + 3) * row_stride);
        const float4 v3 = ldcs4(Vp + (size_t)(s + 3) * row_stride);

        const float sc0 = warp_sum(dot4(k0, q)) * SCALE;
        const float sc1 = warp_sum(dot4(k1, q)) * SCALE;
        const float sc2 = warp_sum(dot4(k2, q)) * SCALE;
        const float sc3 = warp_sum(dot4(k3, q)) * SCALE;

        const float mn = fmaxf(fmaxf(fmaxf(m, sc0), fmaxf(sc1, sc2)), sc3);
        const float corr = __expf(m - mn);
        const float p0 = __expf(sc0 - mn);
        const float p1 = __expf(sc1 - mn);
        const float p2 = __expf(sc2 - mn);
        const float p3 = __expf(sc3 - mn);
        m = mn;
        l = l * corr + ((p0 + p1) + (p2 + p3));
        acc.x = acc.x * corr + (p0 * v0.x + p1 * v1.x) + (p2 * v2.x + p3 * v3.x);
        acc.y = acc.y * corr + (p0 * v0.y + p1 * v1.y) + (p2 * v2.y + p3 * v3.y);
        acc.z = acc.z * corr + (p0 * v0.z + p1 * v1.z) + (p2 * v2.z + p3 * v3.z);
        acc.w = acc.w * corr + (p0 * v0.w + p1 * v1.w) + (p2 * v2.w + p3 * v3.w);
    }
    for (; s < s1; s++) {
        const float4 kk = ldcs4(Kp + (size_t)s * row_stride);
        const float4 vv = ldcs4(Vp + (size_t)s * row_stride);
        const float sc = warp_sum(dot4(kk, q)) * SCALE;
        const float mn   = fmaxf(m, sc);
        const float corr = __expf(m - mn);
        const float p    = __expf(sc - mn);
        m = mn;
        l = l * corr + p;
        acc.x = acc.x * corr + p * vv.x;
        acc.y = acc.y * corr + p * vv.y;
        acc.z = acc.z * corr + p * vv.z;
        acc.w = acc.w * corr + p * vv.w;
    }

    // ---- write this split's partials (single warp: no CTA reduce) ----
    if (lane == 0) { g_pm[bid] = m; g_pl[bid] = l; }
    reinterpret_cast<float4*>(g_pacc + (size_t)bid * DD)[lane] = acc;

    // ---- fused cross-split combine: last CTA per (b,h) merges ----
    __threadfence();
    int done = 0;
    if (lane == 0) done = atomicAdd(&g_cnt[bh], 1);
    done = __shfl_sync(0xffffffffu, done, 0);

    if (done == NSPLITS - 1) {
        float GM = -CUDART_INF_F;
#pragma unroll 8
        for (int i = 0; i < NSPLITS; i++)
            GM = fmaxf(GM, __ldcg(&g_pm[bh * NSPLITS + i]));

        float  GL = 0.f;
        float4 go = make_float4(0.f, 0.f, 0.f, 0.f);
#pragma unroll 4
        for (int i = 0; i < NSPLITS; i++) {
            const int idx = bh * NSPLITS + i;
            const float li = __ldcg(&g_pl[idx]);
            if (li == 0.f) continue;
            const float c = __expf(__ldcg(&g_pm[idx]) - GM);
            GL += c * li;
            const float4 a = __ldcg(reinterpret_cast<const float4*>(
                g_pacc + (size_t)idx * DD) + lane);
            go.x += c * a.x; go.y += c * a.y;
            go.z += c * a.z; go.w += c * a.w;
        }
        const float inv = 1.f / GL;
        const float4 r = make_float4(go.x * inv, go.y * inv,
                                     go.z * inv, go.w * inv);
        reinterpret_cast<float4*>(out + (size_t)bh * DD)[lane] = r;

        if (lane == 0) g_cnt[bh] = 0;   // reset for next graph replay
    }
}

// ---------------------------------------------------------------------------
extern "C" void kernel_launch(void* const* d_in, const int* in_sizes, int n_in,
                              void* d_out, int out_size) {
    // Identify inputs defensively by element count:
    //   x: B*H*D = 16384 fp32, kv: 2*B*S*H*D fp32 (largest), current_pos: 1 int
    const float* x  = nullptr;
    const float* kv = nullptr;
    const int*   cp = nullptr;
    long long best_kv = -1;
    for (int i = 0; i < n_in; i++) {
        if (in_sizes[i] == 1) cp = (const int*)d_in[i];
        else if (in_sizes[i] == BB * HH * DD) x = (const float*)d_in[i];
        else if ((long long)in_sizes[i] > best_kv) {
            best_kv = in_sizes[i];
            kv = (const float*)d_in[i];
        }
    }

    attn_split_kernel<<<NBH * NSPLITS, 32>>>(x, kv, cp, (float*)d_out);
}